// round 15
// baseline (speedup 1.0000x reference)
#include <cuda_runtime.h>
#include <cuda_fp16.h>
#include <math_constants.h>
#include <cstdint>

#define Ln  128
#define Bb  8
#define Dd  256
#define Hh  256
#define NHo 8
#define NGg 50
#define TJ  16
#define ROWS 128
#define TILES ((Ln/TJ)*Ln)   // 1024
#define PAIRS (TILES/2)      // 512

// strides (bytes), odd multiples of 16 -> ldmatrix conflict-free
#define WR_STRB  528
#define WGT_STRB 144
#define WO3_STRB 528

// smem layout: ALL buffers resident, staged once in prologue. No per-tile smem.
#define SM_WR    0                      // 256*528 = 135168  W_res [n][k] fp16
#define SM_WGT   135168                 // 256*144 = 36864   WG^T [n][g] fp16
#define SM_WO3   172032                 // 8*528  = 4224     woutT [o][k] fp16
#define SM_BRES  176256                 // 1024
#define SM_CVEC  177280                 // 1024
#define SM_TOTAL 178304

// prep block decode: 16-row GEMM blocks. 1024 rows / 16 = 64 blocks per matrix.
#define PB_A    64                      // blocks 0..63    -> g_A
#define PB_BV   128                     // blocks 64..127  -> g_Bv
#define PB_WGT  (PB_BV + NGg)           // blocks 128..177 -> WGT rows (178)
#define PB_TOT  (PB_WGT + 1)            // block 178       -> cvec ; grid = 179

// ---- device scratch (no allocs allowed) ----
__device__ float  g_A[Ln*Bb*Hh];      // x @ W1, row l*8+b
__device__ float  g_Bv[Ln*Bb*Hh];     // x @ W2, row l*8+b
__device__ float  g_cvec[Hh];         // b_in + b_rbf @ W3
__device__ __half g_WGT[Hh*64];       // [h][g] = (W_rbf@W3)[g][h], g>=50 zero
__device__ __half g_WresT[Hh*Hh];     // [n][k] = W_res[k][n]

__device__ __forceinline__ uint32_t smem_u32(const void* p) {
    uint32_t a;
    asm("{ .reg .u64 t; cvta.to.shared.u64 t, %1; cvt.u32.u64 %0, t; }" : "=r"(a) : "l"(p));
    return a;
}

__device__ __forceinline__ float gelu_f(float x) {
    float u = 0.7978845608028654f * fmaf(0.044715f * x, x * x, x);
    float t;
    asm("tanh.approx.f32 %0, %1;" : "=f"(t) : "f"(u));
    return 0.5f * x * (1.0f + t);
}

__device__ __forceinline__ void mma16816(float* c, const uint32_t* a, const uint32_t* b) {
    asm volatile(
        "mma.sync.aligned.m16n8k16.row.col.f32.f16.f16.f32 "
        "{%0,%1,%2,%3}, {%4,%5,%6,%7}, {%8,%9}, {%0,%1,%2,%3};"
        : "+f"(c[0]), "+f"(c[1]), "+f"(c[2]), "+f"(c[3])
        : "r"(a[0]), "r"(a[1]), "r"(a[2]), "r"(a[3]), "r"(b[0]), "r"(b[1]));
}

__device__ __forceinline__ void ldsm_x4(uint32_t* r, uint32_t addr) {
    asm volatile("ldmatrix.sync.aligned.m8n8.x4.shared.b16 {%0,%1,%2,%3}, [%4];"
                 : "=r"(r[0]), "=r"(r[1]), "=r"(r[2]), "=r"(r[3]) : "r"(addr));
}
__device__ __forceinline__ void ldsm_x2(uint32_t* r, uint32_t addr) {
    asm volatile("ldmatrix.sync.aligned.m8n8.x2.shared.b16 {%0,%1}, [%2];"
                 : "=r"(r[0]), "=r"(r[1]) : "r"(addr));
}

// ======================= prep: 16-row GEMM blocks (weight stream amortized) ==========
__global__ void __launch_bounds__(256) prep_kernel(
    const float* __restrict__ x,     const float* __restrict__ W_rbf,
    const float* __restrict__ b_rbf, const float* __restrict__ W1,
    const float* __restrict__ W2,    const float* __restrict__ W3,
    const float* __restrict__ b_in)
{
    const int blk = blockIdx.x;
    const int h   = threadIdx.x;

    if (blk < PB_BV) {
        // ---- 16-row block: g_A (blk<64) or g_Bv (64..127) ----
        const float* src; const float* Wm; float* dst;
        if (blk < PB_A) { src = x + (size_t)blk*16*Dd;          Wm = W1; dst = g_A  + (size_t)blk*16*Hh; }
        else            { src = x + (size_t)(blk-PB_A)*16*Dd;   Wm = W2; dst = g_Bv + (size_t)(blk-PB_A)*16*Hh; }

        __shared__ float vsm[16*Dd];
        #pragma unroll
        for (int r = 0; r < 16; r++) vsm[r*Dd + h] = src[r*Dd + h];
        __syncthreads();

        float acc[16];
        #pragma unroll
        for (int r = 0; r < 16; r++) acc[r] = 0.0f;
        #pragma unroll 4
        for (int d = 0; d < Dd; d++) {
            float w = Wm[d*Hh + h];
            #pragma unroll
            for (int r = 0; r < 16; r++) acc[r] = fmaf(vsm[r*Dd + d], w, acc[r]);
        }
        #pragma unroll
        for (int r = 0; r < 16; r++) dst[r*Hh + h] = acc[r];
        return;
    }

    // ---- single-row dot against W3: WGT row (blk<178) or cvec (blk==178) ----
    __shared__ float vsm1[Dd];
    const float* vec = (blk < PB_WGT) ? (W_rbf + (size_t)(blk - PB_BV)*Dd) : b_rbf;
    vsm1[h] = vec[h];
    __syncthreads();
    float acc = 0.0f;
    #pragma unroll 8
    for (int d = 0; d < Dd; d++)
        acc = fmaf(vsm1[d], W3[d*Hh + h], acc);
    if (blk < PB_WGT) {
        g_WGT[h*64 + (blk - PB_BV)] = __float2half(acc);
    } else {
        g_cvec[h] = acc + b_in[h];
        #pragma unroll
        for (int g = NGg; g < 64; g++) g_WGT[h*64 + g] = __float2half(0.0f);
    }
}

// WresT transpose as its own tiny kernel
__global__ void __launch_bounds__(256) prep_wrest_kernel(const float* __restrict__ W_res)
{
    const int k = blockIdx.x;
    const int h = threadIdx.x;
    g_WresT[h*Hh + k] = __float2half(W_res[k*Hh + h]);
}

// ===== persistent fused kernel: tile PAIRS share B-fragments; barrier-free loop =====
__global__ void __launch_bounds__(256, 1) pair_kernel(
    const float* __restrict__ dist, const int* __restrict__ mask,
    const float* __restrict__ b_res, const float* __restrict__ W_out,
    const float* __restrict__ b_out, float* __restrict__ out)
{
    extern __shared__ __align__(16) uint8_t smem[];
    const uint32_t sb = smem_u32(smem);

    const int t    = threadIdx.x;
    const int wid  = t >> 5;
    const int lane = t & 31;
    const int g    = lane >> 2;
    const int tg   = lane & 3;
    const int R0   = wid * 16;          // warp owns tile rows R0..R0+15, ALL 256 cols
    const int lr   = lane & 15;
    const int lcb  = (lane >> 4) * 16;

    float* bres_s = (float*)(smem + SM_BRES);
    float* cvec_s = (float*)(smem + SM_CVEC);

    // ---- prologue: stage ALL resident buffers once ----
    {
        const uint4* ws4 = (const uint4*)g_WresT;     // 256 rows x 32 uint4
        #pragma unroll
        for (int q = 0; q < 32; q++) {
            int u = t + q*256;
            int n = u >> 5, c = u & 31;
            *(uint4*)(smem + SM_WR + n*WR_STRB + c*16) = ws4[u];
        }
        const uint4* wgt4 = (const uint4*)g_WGT;      // 256 rows x 8 uint4
        #pragma unroll
        for (int q = 0; q < 8; q++) {
            int u = t + q*256;
            int n = u >> 3, c = u & 7;
            *(uint4*)(smem + SM_WGT + n*WGT_STRB + c*16) = wgt4[u];
        }
        float4 w0 = *(const float4*)(W_out + t*NHo);
        float4 w1 = *(const float4*)(W_out + t*NHo + 4);
        __half* wo = (__half*)(smem + SM_WO3);
        wo[0*264 + t] = __float2half(w0.x);
        wo[1*264 + t] = __float2half(w0.y);
        wo[2*264 + t] = __float2half(w0.z);
        wo[3*264 + t] = __float2half(w0.w);
        wo[4*264 + t] = __float2half(w1.x);
        wo[5*264 + t] = __float2half(w1.y);
        wo[6*264 + t] = __float2half(w1.z);
        wo[7*264 + t] = __float2half(w1.w);
        bres_s[t] = b_res[t];
        cvec_s[t] = g_cvec[t];
    }
    __syncthreads();    // only barrier; pair loop is barrier-free

    const float delta = 12.0f / 49.0f;
    const float coeff = -0.5f / (delta * delta);

    for (int tp = blockIdx.x; tp < PAIRS; tp += gridDim.x) {
        const int td0 = tp * 2;            // tiles (td0, td0+1): same j0, i and i+1
        const int i0  = td0 & (Ln - 1);
        const int j0  = (td0 >> 7) * TJ;

        // ---- gauss A-frags for BOTH tiles, directly in registers ----
        uint32_t ag[2][4][4];
        #pragma unroll
        for (int tt = 0; tt < 2; tt++) {
            const float d0 = dist[(i0+tt)*(Ln*Bb) + j0*Bb + R0 + g];
            const float d1 = dist[(i0+tt)*(Ln*Bb) + j0*Bb + R0 + g + 8];
            #pragma unroll
            for (int kt = 0; kt < 4; kt++) {
                const int c0 = kt*16 + 2*tg;
                #pragma unroll
                for (int rg = 0; rg < 4; rg++) {
                    const float dd = (rg & 1) ? d1 : d0;
                    const int   ca = c0 + ((rg & 2) ? 8 : 0);
                    float v0 = 0.0f, v1 = 0.0f;
                    if (ca < NGg)     { float e0 = dd - delta*(float)ca;     v0 = __expf(coeff*e0*e0); }
                    if (ca + 1 < NGg) { float e1 = dd - delta*(float)(ca+1); v1 = __expf(coeff*e1*e1); }
                    *(__half2*)&ag[tt][kt][rg] = __floats2half2_rn(v0, v1);
                }
            }
        }

        // ---- MMA1 (both tiles share WGT B-frags) + epilogue-1 -> af1[2] ----
        uint32_t af1[2][16][4];
        #pragma unroll
        for (int nc1 = 0; nc1 < 8; nc1++) {      // 32-col chunks
            float acc1[2][4][4];
            #pragma unroll
            for (int tt = 0; tt < 2; tt++)
                #pragma unroll
                for (int nt = 0; nt < 4; nt++)
                    #pragma unroll
                    for (int e = 0; e < 4; e++) acc1[tt][nt][e] = 0.0f;

            #pragma unroll
            for (int ks = 0; ks < 4; ks++) {
                uint32_t bf[2][4];
                #pragma unroll
                for (int p = 0; p < 2; p++)
                    ldsm_x4(bf[p], sb + SM_WGT + (nc1*32 + p*16 + lr)*WGT_STRB + ks*32 + lcb);
                #pragma unroll
                for (int p = 0; p < 2; p++) {
                    uint32_t be[2] = {bf[p][0], bf[p][2]};
                    uint32_t bo[2] = {bf[p][1], bf[p][3]};
                    #pragma unroll
                    for (int tt = 0; tt < 2; tt++) {
                        mma16816(acc1[tt][2*p],     ag[tt][ks], be);
                        mma16816(acc1[tt][2*p + 1], ag[tt][ks], bo);
                    }
                }
            }

            #pragma unroll
            for (int nt = 0; nt < 4; nt++) {
                const int c = nc1*32 + nt*8 + tg*2;
                // g_A rows shared by both tiles (same j0)
                float2 a0 = *(const float2*)(g_A + (size_t)(j0*Bb + R0 + g)*Hh + c);
                float2 a1 = *(const float2*)(g_A + (size_t)(j0*Bb + R0 + g + 8)*Hh + c);
                float2 cv = *(const float2*)(cvec_s + c);
                const int kt = nc1*2 + (nt >> 1);
                const int jj = (nt & 1) * 2;
                #pragma unroll
                for (int tt = 0; tt < 2; tt++) {
                    float2 bv = *(const float2*)(g_Bv + (size_t)((i0+tt)*Bb + g)*Hh + c);
                    float v0 = acc1[tt][nt][0] + a0.x + bv.x + cv.x;
                    float v1 = acc1[tt][nt][1] + a0.y + bv.y + cv.y;
                    float v2 = acc1[tt][nt][2] + a1.x + bv.x + cv.x;
                    float v3 = acc1[tt][nt][3] + a1.y + bv.y + cv.y;
                    *(__half2*)&af1[tt][kt][jj]     = __floats2half2_rn(gelu_f(v0), gelu_f(v1));
                    *(__half2*)&af1[tt][kt][jj + 1] = __floats2half2_rn(gelu_f(v2), gelu_f(v3));
                }
            }
        }

        // ---- MMA2 (B-frags shared by both tiles, double-buffered) + epi-2 + phase-3 ----
        float acc3[2][4];
        #pragma unroll
        for (int tt = 0; tt < 2; tt++)
            #pragma unroll
            for (int e = 0; e < 4; e++) acc3[tt][e] = 0.0f;

        #pragma unroll
        for (int nc2 = 0; nc2 < 8; nc2++) {
            float acc2[2][4][4];
            #pragma unroll
            for (int tt = 0; tt < 2; tt++)
                #pragma unroll
                for (int nt = 0; nt < 4; nt++)
                    #pragma unroll
                    for (int e = 0; e < 4; e++) acc2[tt][nt][e] = 0.0f;

            uint32_t bfb[2][2][4];       // [buf][p][reg]
            #pragma unroll
            for (int p = 0; p < 2; p++)
                ldsm_x4(bfb[0][p], sb + SM_WR + (nc2*32 + p*16 + lr)*WR_STRB + lcb);

            #pragma unroll
            for (int kt = 0; kt < 16; kt++) {
                const int cur = kt & 1;
                if (kt < 15) {
                    #pragma unroll
                    for (int p = 0; p < 2; p++)
                        ldsm_x4(bfb[cur ^ 1][p],
                                sb + SM_WR + (nc2*32 + p*16 + lr)*WR_STRB + (kt+1)*32 + lcb);
                }
                #pragma unroll
                for (int p = 0; p < 2; p++) {
                    uint32_t be[2] = {bfb[cur][p][0], bfb[cur][p][2]};
                    uint32_t bo[2] = {bfb[cur][p][1], bfb[cur][p][3]};
                    #pragma unroll
                    for (int tt = 0; tt < 2; tt++) {
                        mma16816(acc2[tt][2*p],     af1[tt][kt], be);
                        mma16816(acc2[tt][2*p + 1], af1[tt][kt], bo);
                    }
                }
            }

            // epilogue-2 both tiles -> af2; phase-3 with shared bf3
            uint32_t af2[2][2][4];
            #pragma unroll
            for (int tt = 0; tt < 2; tt++)
                #pragma unroll
                for (int nt = 0; nt < 4; nt++) {
                    const int c = nc2*32 + nt*8 + tg*2;
                    float2 br = *(const float2*)(bres_s + c);
                    const int ktg = nc2*2 + (nt >> 1);
                    const int jj  = (nt & 1) * 2;
                    float2 f0 = __half22float2(*(__half2*)&af1[tt][ktg][jj]);
                    float2 f1 = __half22float2(*(__half2*)&af1[tt][ktg][jj + 1]);
                    float h00 = f0.x + gelu_f(acc2[tt][nt][0] + br.x);
                    float h01 = f0.y + gelu_f(acc2[tt][nt][1] + br.y);
                    float h10 = f1.x + gelu_f(acc2[tt][nt][2] + br.x);
                    float h11 = f1.y + gelu_f(acc2[tt][nt][3] + br.y);
                    *(__half2*)&af2[tt][nt >> 1][jj]     = __floats2half2_rn(h00, h01);
                    *(__half2*)&af2[tt][nt >> 1][jj + 1] = __floats2half2_rn(h10, h11);
                }
            #pragma unroll
            for (int l = 0; l < 2; l++) {
                uint32_t bf3[2];
                ldsm_x2(bf3, sb + SM_WO3 + (lane & 7)*WO3_STRB + (nc2*2 + l)*32
                              + ((lane >> 3) & 1)*16);
                #pragma unroll
                for (int tt = 0; tt < 2; tt++)
                    mma16816(acc3[tt], af2[tt][l], bf3);
            }
        }

        // ---- store both tiles: acc3 + b_out, mask, transposed scatter ----
        {
            float2 bo = *(const float2*)(b_out + tg*2);
            #pragma unroll
            for (int tt = 0; tt < 2; tt++) {
                const int i = i0 + tt;
                #pragma unroll
                for (int h = 0; h < 2; h++) {
                    const int r = R0 + g + h*8;
                    const int b = r & 7;
                    const int j = j0 + (r >> 3);
                    bool m = (mask[b*Ln + i] != 0) && (mask[b*Ln + j] != 0);
                    float v0 = acc3[tt][2*h + 0] + bo.x;
                    float v1 = acc3[tt][2*h + 1] + bo.y;
                    if (!m) { v0 = -CUDART_INF_F; v1 = -CUDART_INF_F; }
                    size_t base = ((size_t)(b*NHo + tg*2))*(Ln*Ln) + (size_t)i*Ln + j;
                    out[base]         = v0;
                    out[base + Ln*Ln] = v1;
                }
            }
        }
    }
}

// ---------------------------------------------------------------------------
extern "C" void kernel_launch(void* const* d_in, const int* in_sizes, int n_in,
                              void* d_out, int out_size) {
    const float* x     = (const float*)d_in[0];
    const float* dist  = (const float*)d_in[1];
    const int*   mask  = (const int*)d_in[2];
    const float* W_rbf = (const float*)d_in[3];
    const float* b_rbf = (const float*)d_in[4];
    const float* W1    = (const float*)d_in[5];
    const float* W2    = (const float*)d_in[6];
    const float* W3    = (const float*)d_in[7];
    const float* b_in  = (const float*)d_in[8];
    const float* W_res = (const float*)d_in[9];
    const float* b_res = (const float*)d_in[10];
    const float* W_out = (const float*)d_in[11];
    const float* b_out = (const float*)d_in[12];
    float*       out   = (float*)d_out;

    prep_kernel<<<PB_TOT, 256>>>(x, W_rbf, b_rbf, W1, W2, W3, b_in);
    prep_wrest_kernel<<<Hh, 256>>>(W_res);

    int sms = 148;
    cudaDeviceGetAttribute(&sms, cudaDevAttrMultiProcessorCount, 0);
    if (sms > PAIRS) sms = PAIRS;

    cudaFuncSetAttribute(pair_kernel, cudaFuncAttributeMaxDynamicSharedMemorySize, SM_TOTAL);
    pair_kernel<<<sms, 256, SM_TOTAL>>>(dist, mask, b_res, W_out, b_out, out);
}

// round 16
// speedup vs baseline: 1.4797x; 1.4797x over previous
#include <cuda_runtime.h>
#include <cuda_fp16.h>
#include <math_constants.h>
#include <cstdint>

#define Ln  128
#define Bb  8
#define Dd  256
#define Hh  256
#define NHo 8
#define NGg 50
#define TJ  16
#define ROWS 128
#define TILES ((Ln/TJ)*Ln)   // 1024

// strides (bytes), odd multiples of 16 -> ldmatrix conflict-free
#define WR_STRB  528
#define WGT_STRB 144
#define WO3_STRB 528

// smem layout: ALL buffers resident, staged once in prologue. No per-tile smem.
#define SM_WR    0                      // 256*528 = 135168  W_res [n][k] fp16
#define SM_WGT   135168                 // 256*144 = 36864   WG^T [n][g] fp16
#define SM_WO3   172032                 // 8*528  = 4224     woutT [o][k] fp16
#define SM_BRES  176256                 // 1024
#define SM_CVEC  177280                 // 1024
#define SM_TOTAL 178304

// prep block decode: 8-row GEMM blocks (1024/8 = 128 per matrix)
#define PB_A     128                    // blocks 0..127   -> g_A
#define PB_BV    256                    // blocks 128..255 -> g_Bv
#define PB_WGT   (PB_BV + NGg)          // blocks 256..305 -> WGT rows
#define PB_CV    PB_WGT                 // block 306       -> cvec
#define PB_WREST (PB_WGT + 1)           // blocks 307..562 -> WresT rows
#define PB_TOT   (PB_WREST + Hh)        // 563

// ---- device scratch (no allocs allowed) ----
__device__ float  g_A[Ln*Bb*Hh];      // x @ W1, row l*8+b
__device__ float  g_Bv[Ln*Bb*Hh];     // x @ W2, row l*8+b
__device__ float  g_cvec[Hh];         // b_in + b_rbf @ W3
__device__ __half g_WGT[Hh*64];       // [h][g] = (W_rbf@W3)[g][h], g>=50 zero
__device__ __half g_WresT[Hh*Hh];     // [n][k] = W_res[k][n]

__device__ __forceinline__ uint32_t smem_u32(const void* p) {
    uint32_t a;
    asm("{ .reg .u64 t; cvta.to.shared.u64 t, %1; cvt.u32.u64 %0, t; }" : "=r"(a) : "l"(p));
    return a;
}

__device__ __forceinline__ float gelu_f(float x) {
    float u = 0.7978845608028654f * fmaf(0.044715f * x, x * x, x);
    float t;
    asm("tanh.approx.f32 %0, %1;" : "=f"(t) : "f"(u));
    return 0.5f * x * (1.0f + t);
}

__device__ __forceinline__ void mma16816(float* c, const uint32_t* a, const uint32_t* b) {
    asm volatile(
        "mma.sync.aligned.m16n8k16.row.col.f32.f16.f16.f32 "
        "{%0,%1,%2,%3}, {%4,%5,%6,%7}, {%8,%9}, {%0,%1,%2,%3};"
        : "+f"(c[0]), "+f"(c[1]), "+f"(c[2]), "+f"(c[3])
        : "r"(a[0]), "r"(a[1]), "r"(a[2]), "r"(a[3]), "r"(b[0]), "r"(b[1]));
}

__device__ __forceinline__ void ldsm_x4(uint32_t* r, uint32_t addr) {
    asm volatile("ldmatrix.sync.aligned.m8n8.x4.shared.b16 {%0,%1,%2,%3}, [%4];"
                 : "=r"(r[0]), "=r"(r[1]), "=r"(r[2]), "=r"(r[3]) : "r"(addr));
}
__device__ __forceinline__ void ldsm_x2(uint32_t* r, uint32_t addr) {
    asm volatile("ldmatrix.sync.aligned.m8n8.x2.shared.b16 {%0,%1}, [%2];"
                 : "=r"(r[0]), "=r"(r[1]) : "r"(addr));
}

// ======= prep: 8-row GEMM blocks, TRANSPOSED x stage (broadcast LDS.128) =======
__global__ void __launch_bounds__(256) prep_kernel(
    const float* __restrict__ x,     const float* __restrict__ W_rbf,
    const float* __restrict__ b_rbf, const float* __restrict__ W1,
    const float* __restrict__ W2,    const float* __restrict__ W3,
    const float* __restrict__ b_in,  const float* __restrict__ W_res)
{
    const int blk = blockIdx.x;
    const int h   = threadIdx.x;

    if (blk >= PB_WREST) {              // WresT transpose rows 0..255
        const int k = blk - PB_WREST;
        g_WresT[h*Hh + k] = __float2half(W_res[k*Hh + h]);
        return;
    }

    if (blk < PB_BV) {
        // ---- 8-row block: g_A (blk<128) or g_Bv ----
        const float* src; const float* Wm; float* dst;
        if (blk < PB_A) { src = x + (size_t)blk*8*Dd;          Wm = W1; dst = g_A  + (size_t)blk*8*Hh; }
        else            { src = x + (size_t)(blk-PB_A)*8*Dd;   Wm = W2; dst = g_Bv + (size_t)(blk-PB_A)*8*Hh; }

        __shared__ float vsmT[Dd*8];    // [d][r] transposed: 8 row-values contiguous
        #pragma unroll
        for (int r = 0; r < 8; r++)
            vsmT[h*8 + r] = src[r*Dd + h];   // coalesced LDG per r
        __syncthreads();

        float acc[8];
        #pragma unroll
        for (int r = 0; r < 8; r++) acc[r] = 0.0f;
        #pragma unroll 4
        for (int d = 0; d < Dd; d++) {
            float w = Wm[d*Hh + h];
            float4 v0 = *(const float4*)(vsmT + d*8);      // broadcast LDS.128
            float4 v1 = *(const float4*)(vsmT + d*8 + 4);
            acc[0] = fmaf(v0.x, w, acc[0]);
            acc[1] = fmaf(v0.y, w, acc[1]);
            acc[2] = fmaf(v0.z, w, acc[2]);
            acc[3] = fmaf(v0.w, w, acc[3]);
            acc[4] = fmaf(v1.x, w, acc[4]);
            acc[5] = fmaf(v1.y, w, acc[5]);
            acc[6] = fmaf(v1.z, w, acc[6]);
            acc[7] = fmaf(v1.w, w, acc[7]);
        }
        #pragma unroll
        for (int r = 0; r < 8; r++) dst[r*Hh + h] = acc[r];
        return;
    }

    // ---- single-row dot against W3: WGT row (blk<306) or cvec (blk==306) ----
    __shared__ float vsm1[Dd];
    const float* vec = (blk < PB_WGT) ? (W_rbf + (size_t)(blk - PB_BV)*Dd) : b_rbf;
    vsm1[h] = vec[h];
    __syncthreads();
    float acc = 0.0f;
    #pragma unroll 8
    for (int d = 0; d < Dd; d++)
        acc = fmaf(vsm1[d], W3[d*Hh + h], acc);
    if (blk < PB_WGT) {
        g_WGT[h*64 + (blk - PB_BV)] = __float2half(acc);
    } else {
        g_cvec[h] = acc + b_in[h];
        #pragma unroll
        for (int g = NGg; g < 64; g++) g_WGT[h*64 + g] = __float2half(0.0f);
    }
}

// ===== persistent fused kernel (round-13 proven): barrier-free, register gauss =====
__global__ void __launch_bounds__(256, 1) pair_kernel(
    const float* __restrict__ dist, const int* __restrict__ mask,
    const float* __restrict__ b_res, const float* __restrict__ W_out,
    const float* __restrict__ b_out, float* __restrict__ out)
{
    extern __shared__ __align__(16) uint8_t smem[];
    const uint32_t sb = smem_u32(smem);

    const int t    = threadIdx.x;
    const int wid  = t >> 5;
    const int lane = t & 31;
    const int g    = lane >> 2;
    const int tg   = lane & 3;
    const int R0   = wid * 16;          // warp owns tile rows R0..R0+15, ALL 256 cols
    const int lr   = lane & 15;
    const int lcb  = (lane >> 4) * 16;

    float* bres_s = (float*)(smem + SM_BRES);
    float* cvec_s = (float*)(smem + SM_CVEC);

    // ---- prologue: stage ALL resident buffers once ----
    {
        const uint4* ws4 = (const uint4*)g_WresT;     // 256 rows x 32 uint4
        #pragma unroll
        for (int q = 0; q < 32; q++) {
            int u = t + q*256;
            int n = u >> 5, c = u & 31;
            *(uint4*)(smem + SM_WR + n*WR_STRB + c*16) = ws4[u];
        }
        const uint4* wgt4 = (const uint4*)g_WGT;      // 256 rows x 8 uint4
        #pragma unroll
        for (int q = 0; q < 8; q++) {
            int u = t + q*256;
            int n = u >> 3, c = u & 7;
            *(uint4*)(smem + SM_WGT + n*WGT_STRB + c*16) = wgt4[u];
        }
        float4 w0 = *(const float4*)(W_out + t*NHo);
        float4 w1 = *(const float4*)(W_out + t*NHo + 4);
        __half* wo = (__half*)(smem + SM_WO3);
        wo[0*264 + t] = __float2half(w0.x);
        wo[1*264 + t] = __float2half(w0.y);
        wo[2*264 + t] = __float2half(w0.z);
        wo[3*264 + t] = __float2half(w0.w);
        wo[4*264 + t] = __float2half(w1.x);
        wo[5*264 + t] = __float2half(w1.y);
        wo[6*264 + t] = __float2half(w1.z);
        wo[7*264 + t] = __float2half(w1.w);
        bres_s[t] = b_res[t];
        cvec_s[t] = g_cvec[t];
    }
    __syncthreads();    // the ONLY barrier: tile loop is barrier-free

    const float delta = 12.0f / 49.0f;
    const float coeff = -0.5f / (delta * delta);

    for (int td = blockIdx.x; td < TILES; td += gridDim.x) {
        const int i  = td & (Ln - 1);
        const int j0 = (td >> 7) * TJ;

        // ---- gauss A-frags computed DIRECTLY in registers ----
        uint32_t ag[4][4];
        {
            const float d0 = dist[i*(Ln*Bb) + j0*Bb + R0 + g];
            const float d1 = dist[i*(Ln*Bb) + j0*Bb + R0 + g + 8];
            #pragma unroll
            for (int kt = 0; kt < 4; kt++) {
                const int c0 = kt*16 + 2*tg;
                #pragma unroll
                for (int rg = 0; rg < 4; rg++) {
                    const float dd = (rg & 1) ? d1 : d0;
                    const int   ca = c0 + ((rg & 2) ? 8 : 0);
                    float v0 = 0.0f, v1 = 0.0f;
                    if (ca < NGg) {
                        float e0 = dd - delta * (float)ca;
                        v0 = __expf(coeff * e0 * e0);
                    }
                    if (ca + 1 < NGg) {
                        float e1 = dd - delta * (float)(ca + 1);
                        v1 = __expf(coeff * e1 * e1);
                    }
                    *(__half2*)&ag[kt][rg] = __floats2half2_rn(v0, v1);
                }
            }
        }

        // ---- MMA1 + epilogue-1: h1 A-frags built in registers ----
        uint32_t af1[16][4];
        #pragma unroll
        for (int nc = 0; nc < 4; nc++) {
            float acc1[8][4];
            #pragma unroll
            for (int nt = 0; nt < 8; nt++)
                #pragma unroll
                for (int e = 0; e < 4; e++) acc1[nt][e] = 0.0f;

            uint32_t bfb[2][2][4];
            #pragma unroll
            for (int p = 0; p < 2; p++)
                ldsm_x4(bfb[0][p], sb + SM_WGT + (nc*64 + p*16 + lr)*WGT_STRB + lcb);

            #pragma unroll
            for (int s = 0; s < 8; s++) {
                const int cur = s & 1;
                if (s < 7) {
                    const int ns = s + 1;
                    const int nks = ns >> 1, nph = ns & 1;
                    #pragma unroll
                    for (int p = 0; p < 2; p++)
                        ldsm_x4(bfb[cur ^ 1][p],
                                sb + SM_WGT + (nc*64 + (nph*2 + p)*16 + lr)*WGT_STRB
                                   + nks*32 + lcb);
                }
                const int ks = s >> 1, ph = s & 1;
                #pragma unroll
                for (int p = 0; p < 2; p++) {
                    const int nt = (ph*2 + p);
                    uint32_t be[2] = {bfb[cur][p][0], bfb[cur][p][2]};
                    uint32_t bo[2] = {bfb[cur][p][1], bfb[cur][p][3]};
                    mma16816(acc1[2*nt],     ag[ks], be);
                    mma16816(acc1[2*nt + 1], ag[ks], bo);
                }
            }

            #pragma unroll
            for (int nt = 0; nt < 8; nt++) {
                const int c = nc*64 + nt*8 + tg*2;
                float2 a0 = *(const float2*)(g_A + (size_t)(j0*Bb + R0 + g)*Hh + c);
                float2 a1 = *(const float2*)(g_A + (size_t)(j0*Bb + R0 + g + 8)*Hh + c);
                float2 bv = *(const float2*)(g_Bv + (size_t)(i*Bb + g)*Hh + c);
                float2 cv = *(const float2*)(cvec_s + c);
                float v0 = acc1[nt][0] + a0.x + bv.x + cv.x;
                float v1 = acc1[nt][1] + a0.y + bv.y + cv.y;
                float v2 = acc1[nt][2] + a1.x + bv.x + cv.x;
                float v3 = acc1[nt][3] + a1.y + bv.y + cv.y;
                const int kt = nc*4 + (nt >> 1);
                const int jj = (nt & 1) * 2;
                *(__half2*)&af1[kt][jj]     = __floats2half2_rn(gelu_f(v0), gelu_f(v1));
                *(__half2*)&af1[kt][jj + 1] = __floats2half2_rn(gelu_f(v2), gelu_f(v3));
            }
        }

        // ---- MMA2 (double-buffered B-frags, 32-col n-chunks) + epi-2 + phase-3 ----
        float acc3[4] = {0.0f, 0.0f, 0.0f, 0.0f};
        #pragma unroll
        for (int nc2 = 0; nc2 < 8; nc2++) {
            float acc2[4][4];
            #pragma unroll
            for (int nt = 0; nt < 4; nt++)
                #pragma unroll
                for (int e = 0; e < 4; e++) acc2[nt][e] = 0.0f;

            uint32_t bfb[2][2][4];
            #pragma unroll
            for (int p = 0; p < 2; p++)
                ldsm_x4(bfb[0][p], sb + SM_WR + (nc2*32 + p*16 + lr)*WR_STRB + lcb);

            #pragma unroll
            for (int kt = 0; kt < 16; kt++) {
                const int cur = kt & 1;
                if (kt < 15) {
                    #pragma unroll
                    for (int p = 0; p < 2; p++)
                        ldsm_x4(bfb[cur ^ 1][p],
                                sb + SM_WR + (nc2*32 + p*16 + lr)*WR_STRB + (kt+1)*32 + lcb);
                }
                #pragma unroll
                for (int p = 0; p < 2; p++) {
                    uint32_t be[2] = {bfb[cur][p][0], bfb[cur][p][2]};
                    uint32_t bo[2] = {bfb[cur][p][1], bfb[cur][p][3]};
                    mma16816(acc2[2*p],     af1[kt], be);
                    mma16816(acc2[2*p + 1], af1[kt], bo);
                }
            }

            uint32_t af2[2][4];
            #pragma unroll
            for (int nt = 0; nt < 4; nt++) {
                const int c = nc2*32 + nt*8 + tg*2;
                float2 br = *(const float2*)(bres_s + c);
                const int ktg = nc2*2 + (nt >> 1);
                const int jj  = (nt & 1) * 2;
                float2 f0 = __half22float2(*(__half2*)&af1[ktg][jj]);
                float2 f1 = __half22float2(*(__half2*)&af1[ktg][jj + 1]);
                float h00 = f0.x + gelu_f(acc2[nt][0] + br.x);
                float h01 = f0.y + gelu_f(acc2[nt][1] + br.y);
                float h10 = f1.x + gelu_f(acc2[nt][2] + br.x);
                float h11 = f1.y + gelu_f(acc2[nt][3] + br.y);
                *(__half2*)&af2[nt >> 1][jj]     = __floats2half2_rn(h00, h01);
                *(__half2*)&af2[nt >> 1][jj + 1] = __floats2half2_rn(h10, h11);
            }
            #pragma unroll
            for (int l = 0; l < 2; l++) {
                uint32_t bf3[2];
                ldsm_x2(bf3, sb + SM_WO3 + (lane & 7)*WO3_STRB + (nc2*2 + l)*32
                              + ((lane >> 3) & 1)*16);
                mma16816(acc3, af2[l], bf3);
            }
        }

        // ---- store: acc3 + b_out, mask, transposed scatter ----
        {
            float2 bo = *(const float2*)(b_out + tg*2);
            #pragma unroll
            for (int h = 0; h < 2; h++) {
                const int r = R0 + g + h*8;
                const int b = r & 7;
                const int j = j0 + (r >> 3);
                bool m = (mask[b*Ln + i] != 0) && (mask[b*Ln + j] != 0);
                float v0 = acc3[2*h + 0] + bo.x;
                float v1 = acc3[2*h + 1] + bo.y;
                if (!m) { v0 = -CUDART_INF_F; v1 = -CUDART_INF_F; }
                size_t base = ((size_t)(b*NHo + tg*2))*(Ln*Ln) + (size_t)i*Ln + j;
                out[base]         = v0;
                out[base + Ln*Ln] = v1;
            }
        }
    }
}

// ---------------------------------------------------------------------------
extern "C" void kernel_launch(void* const* d_in, const int* in_sizes, int n_in,
                              void* d_out, int out_size) {
    const float* x     = (const float*)d_in[0];
    const float* dist  = (const float*)d_in[1];
    const int*   mask  = (const int*)d_in[2];
    const float* W_rbf = (const float*)d_in[3];
    const float* b_rbf = (const float*)d_in[4];
    const float* W1    = (const float*)d_in[5];
    const float* W2    = (const float*)d_in[6];
    const float* W3    = (const float*)d_in[7];
    const float* b_in  = (const float*)d_in[8];
    const float* W_res = (const float*)d_in[9];
    const float* b_res = (const float*)d_in[10];
    const float* W_out = (const float*)d_in[11];
    const float* b_out = (const float*)d_in[12];
    float*       out   = (float*)d_out;

    prep_kernel<<<PB_TOT, 256>>>(x, W_rbf, b_rbf, W1, W2, W3, b_in, W_res);

    int sms = 148;
    cudaDeviceGetAttribute(&sms, cudaDevAttrMultiProcessorCount, 0);
    if (sms > TILES) sms = TILES;

    cudaFuncSetAttribute(pair_kernel, cudaFuncAttributeMaxDynamicSharedMemorySize, SM_TOTAL);
    pair_kernel<<<sms, 256, SM_TOTAL>>>(dist, mask, b_res, W_out, b_out, out);
}